// round 1
// baseline (speedup 1.0000x reference)
#include <cuda_runtime.h>
#include <math.h>

#define NMAX  50000
#define EMB   256
#define MID   256
#define OUTD  128

// ---- scratch (static device globals; no runtime allocation) ----
__device__ float g_H1[NMAX * MID];    // node_emb @ W1
__device__ float g_A1[NMAX * MID];    // aggregated + gelu -> layer-2 input
__device__ float g_H2[NMAX * OUTD];   // X1 @ W2
__device__ float g_dis[NMAX];         // D^-1/2 (in-degree + self loop)
__device__ int   g_deg[NMAX];

// ----------------------------------------------------------------------------
// degree kernels
// ----------------------------------------------------------------------------
__global__ void zero_deg_kernel(int n) {
    int i = blockIdx.x * blockDim.x + threadIdx.x;
    if (i < n) g_deg[i] = 0;
}

__global__ void count_deg_kernel(const int* __restrict__ dst, int E) {
    int e = blockIdx.x * blockDim.x + threadIdx.x;
    if (e < E) atomicAdd(&g_deg[dst[e]], 1);
}

__global__ void compute_dis_kernel(int n) {
    int i = blockIdx.x * blockDim.x + threadIdx.x;
    if (i < n) g_dis[i] = rsqrtf((float)(g_deg[i] + 1));  // +1 = self loop
}

// ----------------------------------------------------------------------------
// fp32 SIMT GEMM:  C[M,N] = A[M,K] @ B[K,N]
// BM=128, BN=64, BK=16, 256 threads, each thread computes 8x4.
// K and N are multiples of 16/64 here (K=256, N=256 or 128); M guarded.
// ----------------------------------------------------------------------------
#define BM 128
#define BN 64
#define BK 16

__global__ __launch_bounds__(256)
void gemm_kernel(const float* __restrict__ A, const float* __restrict__ B,
                 float* __restrict__ C, int M, int N, int K) {
    __shared__ float As[BK][BM + 4];   // +4 pad: conflict-free transpose stores, keeps 16B align
    __shared__ float Bs[BK][BN + 4];

    int tid = threadIdx.x;
    int tx = tid & 15;        // 0..15 -> col group (4 cols each)
    int ty = tid >> 4;        // 0..15 -> row group (8 rows each)

    int m0 = blockIdx.y * BM;
    int n0 = blockIdx.x * BN;

    float acc[8][4];
#pragma unroll
    for (int i = 0; i < 8; i++)
#pragma unroll
        for (int j = 0; j < 4; j++) acc[i][j] = 0.0f;

    for (int k0 = 0; k0 < K; k0 += BK) {
        // load A tile (BM x BK) transposed into As[k][m]; 2048 floats / 256 thr = 8 each
        {
            int aRow = tid >> 1;            // 0..127
            int kk8  = (tid & 1) * 8;       // 0 or 8
            int gm = m0 + aRow;
            if (gm < M) {
                const float* ap = A + (size_t)gm * K + k0 + kk8;
                float4 v0 = *(const float4*)(ap);
                float4 v1 = *(const float4*)(ap + 4);
                As[kk8 + 0][aRow] = v0.x; As[kk8 + 1][aRow] = v0.y;
                As[kk8 + 2][aRow] = v0.z; As[kk8 + 3][aRow] = v0.w;
                As[kk8 + 4][aRow] = v1.x; As[kk8 + 5][aRow] = v1.y;
                As[kk8 + 6][aRow] = v1.z; As[kk8 + 7][aRow] = v1.w;
            } else {
#pragma unroll
                for (int j = 0; j < 8; j++) As[kk8 + j][aRow] = 0.0f;
            }
        }
        // load B tile (BK x BN): 1024 floats / 256 thr = 1 float4 each
        {
            int kk = tid >> 4;              // 0..15
            int nn = (tid & 15) * 4;        // 0..60
            float4 v = *(const float4*)(B + (size_t)(k0 + kk) * N + n0 + nn);
            Bs[kk][nn + 0] = v.x; Bs[kk][nn + 1] = v.y;
            Bs[kk][nn + 2] = v.z; Bs[kk][nn + 3] = v.w;
        }
        __syncthreads();

#pragma unroll
        for (int k = 0; k < BK; k++) {
            float4 a0 = *(const float4*)&As[k][ty * 8];
            float4 a1 = *(const float4*)&As[k][ty * 8 + 4];
            float4 b  = *(const float4*)&Bs[k][tx * 4];
            float ar[8] = {a0.x, a0.y, a0.z, a0.w, a1.x, a1.y, a1.z, a1.w};
            float br[4] = {b.x, b.y, b.z, b.w};
#pragma unroll
            for (int i = 0; i < 8; i++)
#pragma unroll
                for (int j = 0; j < 4; j++)
                    acc[i][j] = fmaf(ar[i], br[j], acc[i][j]);
        }
        __syncthreads();
    }

    // store
#pragma unroll
    for (int i = 0; i < 8; i++) {
        int gm = m0 + ty * 8 + i;
        if (gm < M) {
            float4 v = {acc[i][0], acc[i][1], acc[i][2], acc[i][3]};
            *(float4*)(C + (size_t)gm * N + n0 + tx * 4) = v;
        }
    }
}

// ----------------------------------------------------------------------------
// aggregation init: A[i,:] = H[i,:] * dis[i]^2   (self-loop term)
// ----------------------------------------------------------------------------
__global__ void init_agg_kernel(const float* __restrict__ H, float* __restrict__ Acc,
                                int n, int D) {
    int idx = blockIdx.x * blockDim.x + threadIdx.x;
    if (idx < n * D) {
        int i = idx / D;
        float s = g_dis[i];
        Acc[idx] = H[idx] * s * s;
    }
}

// ----------------------------------------------------------------------------
// edge scatter: one warp per edge, vector-atomic accumulate
// Acc[dst,:] += H[src,:] * dis[src]*dis[dst]
// ----------------------------------------------------------------------------
__global__ __launch_bounds__(256)
void scatter_kernel(const float* __restrict__ H, float* __restrict__ Acc,
                    const int* __restrict__ src, const int* __restrict__ dst,
                    int E, int D) {
    int warp = (blockIdx.x * blockDim.x + threadIdx.x) >> 5;
    int lane = threadIdx.x & 31;
    if (warp >= E) return;
    int s = src[warp];
    int d = dst[warp];
    float norm = g_dis[s] * g_dis[d];
    const float4* hs = (const float4*)(H + (size_t)s * D);
    float4*       ad = (float4*)(Acc + (size_t)d * D);
    int nvec = D >> 2;   // 64 (D=256) or 32 (D=128)
    for (int v = lane; v < nvec; v += 32) {
        float4 h = hs[v];
        float4 m = make_float4(h.x * norm, h.y * norm, h.z * norm, h.w * norm);
        atomicAdd(&ad[v], m);   // RED.v4.f32 on sm_90+
    }
}

// ----------------------------------------------------------------------------
// bias + exact GELU, in place
// ----------------------------------------------------------------------------
__global__ void gelu_bias_kernel(float* __restrict__ X, const float* __restrict__ b,
                                 int n, int D) {
    int idx = blockIdx.x * blockDim.x + threadIdx.x;
    if (idx < n * D) {
        float x = X[idx] + b[idx % D];
        X[idx] = 0.5f * x * (1.0f + erff(x * 0.70710678118654752f));
    }
}

// ----------------------------------------------------------------------------
extern "C" void kernel_launch(void* const* d_in, const int* in_sizes, int n_in,
                              void* d_out, int out_size) {
    const float* node_emb = (const float*)d_in[0];   // [N, 256]
    const float* W1       = (const float*)d_in[1];   // [256, 256]
    const float* b1       = (const float*)d_in[2];   // [256]
    const float* W2       = (const float*)d_in[3];   // [256, 128]
    const float* b2       = (const float*)d_in[4];   // [128]
    const int*   eidx     = (const int*)d_in[5];     // [2, E]

    int N = in_sizes[0] / EMB;
    int E = in_sizes[5] / 2;
    const int* src = eidx;
    const int* dst = eidx + E;

    float* H1 = nullptr; float* A1 = nullptr; float* H2 = nullptr;
    cudaGetSymbolAddress((void**)&H1, g_H1);
    cudaGetSymbolAddress((void**)&A1, g_A1);
    cudaGetSymbolAddress((void**)&H2, g_H2);

    float* outp = (float*)d_out;

    // degrees -> dis
    zero_deg_kernel<<<(N + 255) / 256, 256>>>(N);
    count_deg_kernel<<<(E + 255) / 256, 256>>>(dst, E);
    compute_dis_kernel<<<(N + 255) / 256, 256>>>(N);

    dim3 gblk(256);

    // ---- layer 1 ----
    {
        dim3 grid(MID / BN, (N + BM - 1) / BM);
        gemm_kernel<<<grid, gblk>>>(node_emb, W1, H1, N, MID, EMB);
    }
    init_agg_kernel<<<(N * MID + 255) / 256, 256>>>(H1, A1, N, MID);
    scatter_kernel<<<(E * 32 + 255) / 256, 256>>>(H1, A1, src, dst, E, MID);
    gelu_bias_kernel<<<(N * MID + 255) / 256, 256>>>(A1, b1, N, MID);

    // ---- layer 2 ----
    {
        dim3 grid(OUTD / BN, (N + BM - 1) / BM);
        gemm_kernel<<<grid, gblk>>>(A1, W2, H2, N, OUTD, MID);
    }
    init_agg_kernel<<<(N * OUTD + 255) / 256, 256>>>(H2, outp, N, OUTD);
    scatter_kernel<<<(E * 32 + 255) / 256, 256>>>(H2, outp, src, dst, E, OUTD);
    gelu_bias_kernel<<<(N * OUTD + 255) / 256, 256>>>(outp, b2, N, OUTD);
}

// round 2
// speedup vs baseline: 1.5812x; 1.5812x over previous
#include <cuda_runtime.h>
#include <math.h>

#define NMAX   50000
#define EMAX   1048576
#define EMB    256
#define MID    256
#define OUTD   128

// ---- scratch (static device globals; no runtime allocation) ----
__device__ float g_H1[NMAX * MID];     // dis .* (node_emb @ W1)
__device__ float g_A1[NMAX * MID];     // gelu(agg) -> layer-2 input
__device__ float g_H2[NMAX * OUTD];    // dis .* (A1 @ W2)
__device__ float g_dis[NMAX];          // D^-1/2 (in-degree + self loop)
__device__ int   g_deg[NMAX];
__device__ int   g_rowptr[NMAX + 1];
__device__ int   g_cur[NMAX];
__device__ int   g_col[EMAX];

// ----------------------------------------------------------------------------
// degree / normalization
// ----------------------------------------------------------------------------
__global__ void zero_deg_kernel(int n) {
    int i = blockIdx.x * blockDim.x + threadIdx.x;
    if (i < n) g_deg[i] = 0;
}

__global__ void count_deg_kernel(const int* __restrict__ dst, int E) {
    int e = blockIdx.x * blockDim.x + threadIdx.x;
    if (e < E) atomicAdd(&g_deg[dst[e]], 1);
}

__global__ void compute_dis_kernel(int n) {
    int i = blockIdx.x * blockDim.x + threadIdx.x;
    if (i < n) g_dis[i] = rsqrtf((float)(g_deg[i] + 1));  // +1 = self loop
}

// ----------------------------------------------------------------------------
// single-block exclusive scan of g_deg -> g_rowptr (Hillis-Steele per chunk)
// ----------------------------------------------------------------------------
__global__ __launch_bounds__(1024)
void scan_rowptr_kernel(int n) {
    __shared__ int s[1024];
    __shared__ int carry;
    if (threadIdx.x == 0) carry = 0;
    __syncthreads();
    for (int base = 0; base < n; base += 1024) {
        int i = base + (int)threadIdx.x;
        int v = (i < n) ? g_deg[i] : 0;
        s[threadIdx.x] = v;
        __syncthreads();
#pragma unroll
        for (int off = 1; off < 1024; off <<= 1) {
            int t = (threadIdx.x >= off) ? s[threadIdx.x - off] : 0;
            __syncthreads();
            s[threadIdx.x] += t;
            __syncthreads();
        }
        if (i < n) {
            int ex = carry + s[threadIdx.x] - v;   // exclusive
            g_rowptr[i] = ex;
            g_cur[i] = ex;
        }
        __syncthreads();
        if (threadIdx.x == 1023) carry += s[1023];
        __syncthreads();
    }
    if (threadIdx.x == 0) g_rowptr[n] = carry;
}

// ----------------------------------------------------------------------------
// CSR fill: g_col[rowptr[d] + k] = src  (unordered within a segment -- fine)
// ----------------------------------------------------------------------------
__global__ void fill_csr_kernel(const int* __restrict__ src,
                                const int* __restrict__ dst, int E) {
    int e = blockIdx.x * blockDim.x + threadIdx.x;
    if (e < E) {
        int d = dst[e];
        int pos = atomicAdd(&g_cur[d], 1);
        g_col[pos] = src[e];
    }
}

// ----------------------------------------------------------------------------
// fp32 SIMT GEMM with row-scale epilogue:  C[m,:] = dis[m] * (A @ B)[m,:]
// BM=128, BN=64, BK=16, 256 threads, 8x4 per thread.
// ----------------------------------------------------------------------------
#define BM 128
#define BN 64
#define BK 16

__global__ __launch_bounds__(256)
void gemm_scale_kernel(const float* __restrict__ A, const float* __restrict__ B,
                       float* __restrict__ C, int M, int N, int K) {
    __shared__ float As[BK][BM + 4];
    __shared__ float Bs[BK][BN + 4];

    int tid = threadIdx.x;
    int tx = tid & 15;
    int ty = tid >> 4;

    int m0 = blockIdx.y * BM;
    int n0 = blockIdx.x * BN;

    float acc[8][4];
#pragma unroll
    for (int i = 0; i < 8; i++)
#pragma unroll
        for (int j = 0; j < 4; j++) acc[i][j] = 0.0f;

    for (int k0 = 0; k0 < K; k0 += BK) {
        {
            int aRow = tid >> 1;
            int kk8  = (tid & 1) * 8;
            int gm = m0 + aRow;
            if (gm < M) {
                const float* ap = A + (size_t)gm * K + k0 + kk8;
                float4 v0 = *(const float4*)(ap);
                float4 v1 = *(const float4*)(ap + 4);
                As[kk8 + 0][aRow] = v0.x; As[kk8 + 1][aRow] = v0.y;
                As[kk8 + 2][aRow] = v0.z; As[kk8 + 3][aRow] = v0.w;
                As[kk8 + 4][aRow] = v1.x; As[kk8 + 5][aRow] = v1.y;
                As[kk8 + 6][aRow] = v1.z; As[kk8 + 7][aRow] = v1.w;
            } else {
#pragma unroll
                for (int j = 0; j < 8; j++) As[kk8 + j][aRow] = 0.0f;
            }
        }
        {
            int kk = tid >> 4;
            int nn = (tid & 15) * 4;
            float4 v = *(const float4*)(B + (size_t)(k0 + kk) * N + n0 + nn);
            Bs[kk][nn + 0] = v.x; Bs[kk][nn + 1] = v.y;
            Bs[kk][nn + 2] = v.z; Bs[kk][nn + 3] = v.w;
        }
        __syncthreads();

#pragma unroll
        for (int k = 0; k < BK; k++) {
            float4 a0 = *(const float4*)&As[k][ty * 8];
            float4 a1 = *(const float4*)&As[k][ty * 8 + 4];
            float4 b  = *(const float4*)&Bs[k][tx * 4];
            float ar[8] = {a0.x, a0.y, a0.z, a0.w, a1.x, a1.y, a1.z, a1.w};
            float br[4] = {b.x, b.y, b.z, b.w};
#pragma unroll
            for (int i = 0; i < 8; i++)
#pragma unroll
                for (int j = 0; j < 4; j++)
                    acc[i][j] = fmaf(ar[i], br[j], acc[i][j]);
        }
        __syncthreads();
    }

#pragma unroll
    for (int i = 0; i < 8; i++) {
        int gm = m0 + ty * 8 + i;
        if (gm < M) {
            float s = g_dis[gm];
            float4 v = {acc[i][0] * s, acc[i][1] * s, acc[i][2] * s, acc[i][3] * s};
            *(float4*)(C + (size_t)gm * N + n0 + tx * 4) = v;
        }
    }
}

// ----------------------------------------------------------------------------
// pull aggregation + bias + exact GELU
// Out[d,:] = gelu( dis[d] * (Hs[d,:] + sum_{s in N(d)} Hs[s,:]) + bias )
// TPG threads per node; each thread owns one float4 (D = TPG*4).
// ----------------------------------------------------------------------------
__device__ __forceinline__ float4 f4add(float4 a, float4 b) {
    return make_float4(a.x + b.x, a.y + b.y, a.z + b.z, a.w + b.w);
}

template <int TPG>
__global__ __launch_bounds__(256)
void agg_gelu_kernel(const float* __restrict__ Hs, const float* __restrict__ bias,
                     float* __restrict__ Out, int n) {
    int gid = (int)(blockIdx.x * blockDim.x + threadIdx.x) / TPG;  // node
    int t   = threadIdx.x & (TPG - 1);                             // float4 slot
    if (gid >= n) return;

    const float4* H4 = (const float4*)Hs;
    int beg = g_rowptr[gid];
    int end = g_rowptr[gid + 1];

    float4 a0 = H4[(size_t)gid * TPG + t];   // self-loop term
    float4 a1 = make_float4(0.f, 0.f, 0.f, 0.f);
    float4 a2 = a1, a3 = a1;

    int p = beg;
    for (; p + 3 < end; p += 4) {
        int s0 = g_col[p];
        int s1 = g_col[p + 1];
        int s2 = g_col[p + 2];
        int s3 = g_col[p + 3];
        a0 = f4add(a0, H4[(size_t)s0 * TPG + t]);
        a1 = f4add(a1, H4[(size_t)s1 * TPG + t]);
        a2 = f4add(a2, H4[(size_t)s2 * TPG + t]);
        a3 = f4add(a3, H4[(size_t)s3 * TPG + t]);
    }
    for (; p < end; p++)
        a0 = f4add(a0, H4[(size_t)g_col[p] * TPG + t]);

    float4 acc = f4add(f4add(a0, a1), f4add(a2, a3));
    float dd = g_dis[gid];
    float4 bb = ((const float4*)bias)[t];

    float x0 = acc.x * dd + bb.x;
    float x1 = acc.y * dd + bb.y;
    float x2 = acc.z * dd + bb.z;
    float x3 = acc.w * dd + bb.w;
    const float inv_sqrt2 = 0.70710678118654752f;
    float4 o;
    o.x = 0.5f * x0 * (1.0f + erff(x0 * inv_sqrt2));
    o.y = 0.5f * x1 * (1.0f + erff(x1 * inv_sqrt2));
    o.z = 0.5f * x2 * (1.0f + erff(x2 * inv_sqrt2));
    o.w = 0.5f * x3 * (1.0f + erff(x3 * inv_sqrt2));
    ((float4*)Out)[(size_t)gid * TPG + t] = o;
}

// ----------------------------------------------------------------------------
extern "C" void kernel_launch(void* const* d_in, const int* in_sizes, int n_in,
                              void* d_out, int out_size) {
    const float* node_emb = (const float*)d_in[0];   // [N, 256]
    const float* W1       = (const float*)d_in[1];   // [256, 256]
    const float* b1       = (const float*)d_in[2];   // [256]
    const float* W2       = (const float*)d_in[3];   // [256, 128]
    const float* b2       = (const float*)d_in[4];   // [128]
    const int*   eidx     = (const int*)d_in[5];     // [2, E]

    int N = in_sizes[0] / EMB;
    int E = in_sizes[5] / 2;
    const int* src = eidx;
    const int* dst = eidx + E;

    float* H1 = nullptr; float* A1 = nullptr; float* H2 = nullptr;
    cudaGetSymbolAddress((void**)&H1, g_H1);
    cudaGetSymbolAddress((void**)&A1, g_A1);
    cudaGetSymbolAddress((void**)&H2, g_H2);
    float* outp = (float*)d_out;

    // ---- degrees, normalization, CSR (independent of GEMM inputs) ----
    zero_deg_kernel<<<(N + 255) / 256, 256>>>(N);
    count_deg_kernel<<<(E + 255) / 256, 256>>>(dst, E);
    compute_dis_kernel<<<(N + 255) / 256, 256>>>(N);
    scan_rowptr_kernel<<<1, 1024>>>(N);
    fill_csr_kernel<<<(E + 255) / 256, 256>>>(src, dst, E);

    // ---- layer 1: Hs1 = dis .* (node_emb @ W1); A1 = gelu(agg + b1) ----
    {
        dim3 grid(MID / BN, (N + BM - 1) / BM);
        gemm_scale_kernel<<<grid, 256>>>(node_emb, W1, H1, N, MID, EMB);
    }
    {
        const int TPG = MID / 4;  // 64 threads per node
        int groups_per_blk = 256 / TPG;
        int nblk = (N + groups_per_blk - 1) / groups_per_blk;
        agg_gelu_kernel<TPG><<<nblk, 256>>>(H1, b1, A1, N);
    }

    // ---- layer 2: Hs2 = dis .* (A1 @ W2); out = gelu(agg + b2) ----
    {
        dim3 grid(OUTD / BN, (N + BM - 1) / BM);
        gemm_scale_kernel<<<grid, 256>>>(A1, W2, H2, N, OUTD, MID);
    }
    {
        const int TPG = OUTD / 4;  // 32 threads per node
        int groups_per_blk = 256 / TPG;
        int nblk = (N + groups_per_blk - 1) / groups_per_blk;
        agg_gelu_kernel<TPG><<<nblk, 256>>>(H2, b2, outp, N);
    }
}